// round 1
// baseline (speedup 1.0000x reference)
#include <cuda_runtime.h>

#define N_NODES 100000
#define N_EDGES 1600000
#define D_IN    480
#define D_OUT   256
#define NEG_SLOPE 0.2f

// ---------------- scratch (device globals: alloc-free) ----------------
__device__ float    g_xl[(size_t)N_NODES * D_OUT];   // x @ W_l + b_l
__device__ float    g_xr[(size_t)N_NODES * D_OUT];   // x @ W_r + b_r
__device__ float    g_elog[N_EDGES];                 // attention logits
__device__ float    g_exv[N_EDGES];                  // exp(e - max)
__device__ unsigned g_emax[N_NODES];                 // ordered-uint float max
__device__ float    g_denom[N_NODES];
__device__ int      g_counts[N_NODES];
__device__ int      g_offs[N_NODES];                 // CSR start offsets
__device__ int      g_wpos[N_NODES];                 // write cursors
__device__ int      g_perm[N_EDGES];                 // edges grouped by dst
__device__ int      g_bsum[128];
__device__ int      g_bsum_ex[128];

// monotone float <-> uint mapping for atomicMax on floats
__device__ __forceinline__ unsigned ford(float f) {
    unsigned u = __float_as_uint(f);
    return (u & 0x80000000u) ? ~u : (u | 0x80000000u);
}
__device__ __forceinline__ float finv(unsigned u) {
    return (u & 0x80000000u) ? __uint_as_float(u & 0x7fffffffu)
                             : __uint_as_float(~u);
}

// ---------------- K0: init ----------------
__global__ void init_kernel() {
    int i = blockIdx.x * blockDim.x + threadIdx.x;
    if (i < N_NODES) {
        g_emax[i]   = 0u;     // decodes below any real value update
        g_denom[i]  = 0.f;
        g_counts[i] = 0;
    }
}

// ---------------- K1: fused dual GEMM  Y = X*W + b ----------------
// Combined column space: cols [0,256) -> W_l/b_l -> g_xl ; [256,512) -> W_r/b_r -> g_xr
#define BM 64
#define BN 64
#define BK 16
#define PAD_STRIDE 68   // multiple of 4 (float4 align), 68 % 32 = 4 -> only 2-way store conflicts

__global__ void gemm_kernel(const float* __restrict__ X,
                            const float* __restrict__ W_l, const float* __restrict__ b_l,
                            const float* __restrict__ W_r, const float* __restrict__ b_r) {
    __shared__ float As[BK * PAD_STRIDE];   // As[k][m]
    __shared__ float Bs[BK * PAD_STRIDE];   // Bs[k][n]

    int tx   = threadIdx.x;                 // 0..255
    int row0 = blockIdx.y * BM;
    int col0 = blockIdx.x * BN;             // 0..511

    const float* W; const float* bv; float* Y;
    int wc = col0;
    if (col0 < D_OUT) { W = W_l; bv = b_l; Y = g_xl; }
    else              { W = W_r; bv = b_r; Y = g_xr; wc = col0 - D_OUT; }

    int tr = tx >> 4;        // 0..15
    int tc = tx & 15;        // 0..15

    float acc[4][4];
#pragma unroll
    for (int i = 0; i < 4; i++)
#pragma unroll
        for (int j = 0; j < 4; j++) acc[i][j] = 0.f;

    for (int k0 = 0; k0 < D_IN; k0 += BK) {
        // load A tile: 64 rows x 16 k.  idx -> (m = idx>>4, k = idx&15): 16 consecutive k per row
#pragma unroll
        for (int i = 0; i < 4; i++) {
            int idx = tx + i * 256;
            int k = idx & 15, m = idx >> 4;
            int gr = row0 + m;
            As[k * PAD_STRIDE + m] =
                (gr < N_NODES) ? X[(size_t)gr * D_IN + k0 + k] : 0.f;
        }
        // load B tile: 16 k x 64 n.  idx -> (k = idx>>6, n = idx&63): coalesced on n
#pragma unroll
        for (int i = 0; i < 4; i++) {
            int idx = tx + i * 256;
            int n = idx & 63, k = idx >> 6;
            Bs[k * PAD_STRIDE + n] = W[(size_t)(k0 + k) * D_OUT + wc + n];
        }
        __syncthreads();

#pragma unroll
        for (int k = 0; k < BK; k++) {
            float4 a = *reinterpret_cast<const float4*>(&As[k * PAD_STRIDE + tr * 4]);
            float4 b = *reinterpret_cast<const float4*>(&Bs[k * PAD_STRIDE + tc * 4]);
            float av[4] = {a.x, a.y, a.z, a.w};
            float bvv[4] = {b.x, b.y, b.z, b.w};
#pragma unroll
            for (int i = 0; i < 4; i++)
#pragma unroll
                for (int j = 0; j < 4; j++)
                    acc[i][j] = fmaf(av[i], bvv[j], acc[i][j]);
        }
        __syncthreads();
    }

#pragma unroll
    for (int i = 0; i < 4; i++) {
        int gr = row0 + tr * 4 + i;
        if (gr < N_NODES) {
#pragma unroll
            for (int j = 0; j < 4; j++) {
                int gc = wc + tc * 4 + j;
                Y[(size_t)gr * D_OUT + gc] = acc[i][j] + bv[gc];
            }
        }
    }
}

// ---------------- K2: edge logits + segment max + degree histogram ----------------
// one warp per edge
__global__ void edge_logits_kernel(const int* __restrict__ ei,
                                   const float* __restrict__ att) {
    int e = blockIdx.x * 8 + (threadIdx.x >> 5);
    if (e >= N_EDGES) return;
    int lane = threadIdx.x & 31;
    int s = ei[e];
    int d = ei[N_EDGES + e];

    const float4* xl = reinterpret_cast<const float4*>(g_xl + (size_t)s * D_OUT);
    const float4* xr = reinterpret_cast<const float4*>(g_xr + (size_t)d * D_OUT);
    const float4* at = reinterpret_cast<const float4*>(att);

    float sum = 0.f;
#pragma unroll
    for (int i = 0; i < 2; i++) {
        int idx = lane + 32 * i;
        float4 a = xl[idx];
        float4 b = xr[idx];
        float4 c = at[idx];
        float h;
        h = a.x + b.x; h = h > 0.f ? h : NEG_SLOPE * h; sum = fmaf(c.x, h, sum);
        h = a.y + b.y; h = h > 0.f ? h : NEG_SLOPE * h; sum = fmaf(c.y, h, sum);
        h = a.z + b.z; h = h > 0.f ? h : NEG_SLOPE * h; sum = fmaf(c.z, h, sum);
        h = a.w + b.w; h = h > 0.f ? h : NEG_SLOPE * h; sum = fmaf(c.w, h, sum);
    }
#pragma unroll
    for (int o = 16; o > 0; o >>= 1) sum += __shfl_xor_sync(0xffffffffu, sum, o);

    if (lane == 0) {
        g_elog[e] = sum;
        atomicMax(&g_emax[d], ford(sum));
        atomicAdd(&g_counts[d], 1);
    }
}

// ---------------- K3a/b/c: exclusive scan of counts -> offsets ----------------
#define SCAN_CH 1024
#define SCAN_NBLK ((N_NODES + SCAN_CH - 1) / SCAN_CH)   // 98

__global__ void scan1_kernel() {
    __shared__ int sh[SCAN_CH];
    int t = threadIdx.x;
    int g = blockIdx.x * SCAN_CH + t;
    int v = (g < N_NODES) ? g_counts[g] : 0;
    sh[t] = v;
    __syncthreads();
    for (int o = 1; o < SCAN_CH; o <<= 1) {
        int x = (t >= o) ? sh[t - o] : 0;
        __syncthreads();
        sh[t] += x;
        __syncthreads();
    }
    if (g < N_NODES) g_offs[g] = sh[t] - v;   // exclusive within block
    if (t == SCAN_CH - 1) g_bsum[blockIdx.x] = sh[t];
}

__global__ void scan2_kernel() {
    int acc = 0;
    for (int i = 0; i < SCAN_NBLK; i++) {
        g_bsum_ex[i] = acc;
        acc += g_bsum[i];
    }
}

__global__ void scan3_kernel() {
    int g = blockIdx.x * SCAN_CH + threadIdx.x;
    if (g < N_NODES) {
        int v = g_offs[g] + g_bsum_ex[blockIdx.x];
        g_offs[g] = v;
        g_wpos[g] = v;
    }
}

// ---------------- K4: exp, denom, CSR scatter ----------------
__global__ void edge_exp_kernel(const int* __restrict__ ei) {
    int e = blockIdx.x * blockDim.x + threadIdx.x;
    if (e >= N_EDGES) return;
    int d = ei[N_EDGES + e];
    float m  = finv(g_emax[d]);
    float ex = __expf(g_elog[e] - m);
    g_exv[e] = ex;
    atomicAdd(&g_denom[d], ex);
    int pos = atomicAdd(&g_wpos[d], 1);
    g_perm[pos] = e;
}

// ---------------- K5: per-node weighted aggregation (one warp per node) ----------------
__global__ void aggregate_kernel(const int* __restrict__ ei,
                                 const float* __restrict__ bias,
                                 float* __restrict__ out) {
    int node = blockIdx.x * 4 + (threadIdx.x >> 5);
    if (node >= N_NODES) return;
    int lane = threadIdx.x & 31;
    int beg = g_offs[node];
    int cnt = g_counts[node];

    float4 acc0 = make_float4(0.f, 0.f, 0.f, 0.f);
    float4 acc1 = make_float4(0.f, 0.f, 0.f, 0.f);

    for (int j = 0; j < cnt; j++) {
        int e = g_perm[beg + j];
        int s = ei[e];
        float w = g_exv[e];
        const float4* xl = reinterpret_cast<const float4*>(g_xl + (size_t)s * D_OUT);
        float4 a = xl[lane];
        float4 b = xl[lane + 32];
        acc0.x = fmaf(w, a.x, acc0.x); acc0.y = fmaf(w, a.y, acc0.y);
        acc0.z = fmaf(w, a.z, acc0.z); acc0.w = fmaf(w, a.w, acc0.w);
        acc1.x = fmaf(w, b.x, acc1.x); acc1.y = fmaf(w, b.y, acc1.y);
        acc1.z = fmaf(w, b.z, acc1.z); acc1.w = fmaf(w, b.w, acc1.w);
    }

    float rd = 1.f / (g_denom[node] + 1e-16f);
    const float4* bi = reinterpret_cast<const float4*>(bias);
    float4 b0 = bi[lane], b1 = bi[lane + 32];
    float4 o0 = make_float4(fmaf(acc0.x, rd, b0.x), fmaf(acc0.y, rd, b0.y),
                            fmaf(acc0.z, rd, b0.z), fmaf(acc0.w, rd, b0.w));
    float4 o1 = make_float4(fmaf(acc1.x, rd, b1.x), fmaf(acc1.y, rd, b1.y),
                            fmaf(acc1.z, rd, b1.z), fmaf(acc1.w, rd, b1.w));
    float4* op = reinterpret_cast<float4*>(out + (size_t)node * D_OUT);
    op[lane]      = o0;
    op[lane + 32] = o1;
}

// ---------------- launch ----------------
extern "C" void kernel_launch(void* const* d_in, const int* in_sizes, int n_in,
                              void* d_out, int out_size) {
    const float* x    = (const float*)d_in[0];
    const int*   ei   = (const int*)d_in[1];
    const float* W_l  = (const float*)d_in[2];
    const float* b_l  = (const float*)d_in[3];
    const float* W_r  = (const float*)d_in[4];
    const float* b_r  = (const float*)d_in[5];
    const float* att  = (const float*)d_in[6];
    const float* bias = (const float*)d_in[7];
    float* out = (float*)d_out;

    init_kernel<<<(N_NODES + 255) / 256, 256>>>();

    dim3 ggrid(2 * D_OUT / BN, (N_NODES + BM - 1) / BM);   // (8, 1563)
    gemm_kernel<<<ggrid, 256>>>(x, W_l, b_l, W_r, b_r);

    edge_logits_kernel<<<(N_EDGES + 7) / 8, 256>>>(ei, att);

    scan1_kernel<<<SCAN_NBLK, SCAN_CH>>>();
    scan2_kernel<<<1, 1>>>();
    scan3_kernel<<<SCAN_NBLK, SCAN_CH>>>();

    edge_exp_kernel<<<(N_EDGES + 255) / 256, 256>>>(ei);

    aggregate_kernel<<<(N_NODES + 3) / 4, 128>>>(ei, bias, out);
}

// round 2
// speedup vs baseline: 2.1242x; 2.1242x over previous
#include <cuda_runtime.h>

#define N_NODES 100000
#define N_EDGES 1600000
#define D_IN    480
#define D_OUT   256
#define NEG_SLOPE 0.2f

// ---------------- scratch (device globals: alloc-free) ----------------
__device__ float    g_xl[(size_t)N_NODES * D_OUT];   // x @ W_l + b_l
__device__ float    g_xr[(size_t)N_NODES * D_OUT];   // x @ W_r + b_r
__device__ float    g_elog[N_EDGES];                 // attention logits
__device__ float    g_exv[N_EDGES];                  // exp(e - max)
__device__ unsigned g_emax[N_NODES];                 // ordered-uint float max
__device__ float    g_denom[N_NODES];
__device__ int      g_counts[N_NODES];
__device__ int      g_offs[N_NODES];                 // CSR start offsets
__device__ int      g_wpos[N_NODES];                 // write cursors
__device__ int      g_perm[N_EDGES];                 // edges grouped by dst
__device__ int      g_bsum[128];
__device__ int      g_bsum_ex[128];

// monotone float <-> uint mapping for atomicMax on floats
__device__ __forceinline__ unsigned ford(float f) {
    unsigned u = __float_as_uint(f);
    return (u & 0x80000000u) ? ~u : (u | 0x80000000u);
}
__device__ __forceinline__ float finv(unsigned u) {
    return (u & 0x80000000u) ? __uint_as_float(u & 0x7fffffffu)
                             : __uint_as_float(~u);
}

__device__ __forceinline__ float tf32r(float x) {
    unsigned r;
    asm("cvt.rna.tf32.f32 %0, %1;" : "=r"(r) : "f"(x));
    return __uint_as_float(r);
}

// ---------------- K0: init ----------------
__global__ void init_kernel() {
    int i = blockIdx.x * blockDim.x + threadIdx.x;
    if (i < N_NODES) {
        g_emax[i]   = 0u;
        g_denom[i]  = 0.f;
        g_counts[i] = 0;
    }
}

// ---------------- K1: fused dual GEMM via tf32 mma.sync ----------------
// Combined column space [0,512): [0,256)->W_l/b_l->g_xl ; [256,512)->W_r/b_r->g_xr
// Block tile 128x128, BK=32, 8 warps each 32(m) x 64(n).
#define GBM 128
#define GBN 128
#define GBK 32
#define PADA 36    // bank = (4*row + k) % 32 -> conflict-free frag loads
#define PADB 136   // bank = (8*k + n) % 32   -> conflict-free frag loads

__global__ __launch_bounds__(256, 2)
void gemm_tf32_kernel(const float* __restrict__ X,
                      const float* __restrict__ W_l, const float* __restrict__ b_l,
                      const float* __restrict__ W_r, const float* __restrict__ b_r) {
    __shared__ float As[GBM * PADA];     // As[m][k]
    __shared__ float Bs[GBK * PADB];     // Bs[k][n]

    int tx   = threadIdx.x;
    int lane = tx & 31;
    int wid  = tx >> 5;
    int warp_m = wid & 3;       // 0..3  (rows of 32)
    int warp_n = wid >> 2;      // 0..1  (cols of 64)

    int row0 = blockIdx.y * GBM;
    int col0 = blockIdx.x * GBN;    // 0,128,256,384

    const float* W; const float* bv; float* Y;
    int wc = col0;
    if (col0 < D_OUT) { W = W_l; bv = b_l; Y = g_xl; }
    else              { W = W_r; bv = b_r; Y = g_xr; wc = col0 - D_OUT; }

    float acc[2][8][4];
#pragma unroll
    for (int mt = 0; mt < 2; mt++)
#pragma unroll
        for (int nt = 0; nt < 8; nt++)
#pragma unroll
            for (int i = 0; i < 4; i++) acc[mt][nt][i] = 0.f;

    for (int k0 = 0; k0 < D_IN; k0 += GBK) {
        // A tile: 128 rows x 32 k -> 1024 float4; thread does 4
#pragma unroll
        for (int i = 0; i < 4; i++) {
            int f  = tx + i * 256;
            int m  = f >> 3;          // 0..127
            int kq = f & 7;           // float4 index in k
            int gr = row0 + m;
            float4 v = make_float4(0.f, 0.f, 0.f, 0.f);
            if (gr < N_NODES)
                v = *reinterpret_cast<const float4*>(X + (size_t)gr * D_IN + k0 + kq * 4);
            v.x = tf32r(v.x); v.y = tf32r(v.y); v.z = tf32r(v.z); v.w = tf32r(v.w);
            *reinterpret_cast<float4*>(&As[m * PADA + kq * 4]) = v;
        }
        // B tile: 32 k x 128 n -> 1024 float4; thread does 4
#pragma unroll
        for (int i = 0; i < 4; i++) {
            int f  = tx + i * 256;
            int k  = f >> 5;          // 0..31
            int nq = f & 31;          // float4 index in n
            float4 v = *reinterpret_cast<const float4*>(W + (size_t)(k0 + k) * D_OUT + wc + nq * 4);
            v.x = tf32r(v.x); v.y = tf32r(v.y); v.z = tf32r(v.z); v.w = tf32r(v.w);
            *reinterpret_cast<float4*>(&Bs[k * PADB + nq * 4]) = v;
        }
        __syncthreads();

#pragma unroll
        for (int ks = 0; ks < 4; ks++) {
            int kb = ks * 8;
            int kk = kb + (lane & 3);
            unsigned a[2][4];
#pragma unroll
            for (int mt = 0; mt < 2; mt++) {
                int r = warp_m * 32 + mt * 16 + (lane >> 2);
                a[mt][0] = __float_as_uint(As[r * PADA + kk]);
                a[mt][1] = __float_as_uint(As[(r + 8) * PADA + kk]);
                a[mt][2] = __float_as_uint(As[r * PADA + kk + 4]);
                a[mt][3] = __float_as_uint(As[(r + 8) * PADA + kk + 4]);
            }
#pragma unroll
            for (int nt = 0; nt < 8; nt++) {
                int n = warp_n * 64 + nt * 8 + (lane >> 2);
                unsigned b0 = __float_as_uint(Bs[kk * PADB + n]);
                unsigned b1 = __float_as_uint(Bs[(kk + 4) * PADB + n]);
#pragma unroll
                for (int mt = 0; mt < 2; mt++) {
                    asm volatile(
                        "mma.sync.aligned.m16n8k8.row.col.f32.tf32.tf32.f32 "
                        "{%0,%1,%2,%3}, {%4,%5,%6,%7}, {%8,%9}, {%0,%1,%2,%3};"
                        : "+f"(acc[mt][nt][0]), "+f"(acc[mt][nt][1]),
                          "+f"(acc[mt][nt][2]), "+f"(acc[mt][nt][3])
                        : "r"(a[mt][0]), "r"(a[mt][1]), "r"(a[mt][2]), "r"(a[mt][3]),
                          "r"(b0), "r"(b1));
                }
            }
        }
        __syncthreads();
    }

    // epilogue: c0,c1 -> (row, col..col+1); c2,c3 -> (row+8, col..col+1)
#pragma unroll
    for (int mt = 0; mt < 2; mt++) {
        int r = row0 + warp_m * 32 + mt * 16 + (lane >> 2);
#pragma unroll
        for (int nt = 0; nt < 8; nt++) {
            int c = wc + warp_n * 64 + nt * 8 + (lane & 3) * 2;
            if (r < N_NODES) {
                float2 v;
                v.x = acc[mt][nt][0] + bv[c];
                v.y = acc[mt][nt][1] + bv[c + 1];
                *reinterpret_cast<float2*>(Y + (size_t)r * D_OUT + c) = v;
            }
            if (r + 8 < N_NODES) {
                float2 v;
                v.x = acc[mt][nt][2] + bv[c];
                v.y = acc[mt][nt][3] + bv[c + 1];
                *reinterpret_cast<float2*>(Y + (size_t)(r + 8) * D_OUT + c) = v;
            }
        }
    }
}

// ---------------- K2: edge logits + segment max + degree histogram ----------------
__global__ void edge_logits_kernel(const int* __restrict__ ei,
                                   const float* __restrict__ att) {
    int e = blockIdx.x * 8 + (threadIdx.x >> 5);
    if (e >= N_EDGES) return;
    int lane = threadIdx.x & 31;
    int s = ei[e];
    int d = ei[N_EDGES + e];

    const float4* xl = reinterpret_cast<const float4*>(g_xl + (size_t)s * D_OUT);
    const float4* xr = reinterpret_cast<const float4*>(g_xr + (size_t)d * D_OUT);
    const float4* at = reinterpret_cast<const float4*>(att);

    float sum = 0.f;
#pragma unroll
    for (int i = 0; i < 2; i++) {
        int idx = lane + 32 * i;
        float4 a = xl[idx];
        float4 b = xr[idx];
        float4 c = at[idx];
        float h;
        h = a.x + b.x; h = h > 0.f ? h : NEG_SLOPE * h; sum = fmaf(c.x, h, sum);
        h = a.y + b.y; h = h > 0.f ? h : NEG_SLOPE * h; sum = fmaf(c.y, h, sum);
        h = a.z + b.z; h = h > 0.f ? h : NEG_SLOPE * h; sum = fmaf(c.z, h, sum);
        h = a.w + b.w; h = h > 0.f ? h : NEG_SLOPE * h; sum = fmaf(c.w, h, sum);
    }
#pragma unroll
    for (int o = 16; o > 0; o >>= 1) sum += __shfl_xor_sync(0xffffffffu, sum, o);

    if (lane == 0) {
        g_elog[e] = sum;
        atomicMax(&g_emax[d], ford(sum));
        atomicAdd(&g_counts[d], 1);
    }
}

// ---------------- K3a/b/c: exclusive scan of counts -> offsets ----------------
#define SCAN_CH 1024
#define SCAN_NBLK ((N_NODES + SCAN_CH - 1) / SCAN_CH)   // 98

__global__ void scan1_kernel() {
    __shared__ int sh[SCAN_CH];
    int t = threadIdx.x;
    int g = blockIdx.x * SCAN_CH + t;
    int v = (g < N_NODES) ? g_counts[g] : 0;
    sh[t] = v;
    __syncthreads();
    for (int o = 1; o < SCAN_CH; o <<= 1) {
        int x = (t >= o) ? sh[t - o] : 0;
        __syncthreads();
        sh[t] += x;
        __syncthreads();
    }
    if (g < N_NODES) g_offs[g] = sh[t] - v;
    if (t == SCAN_CH - 1) g_bsum[blockIdx.x] = sh[t];
}

__global__ void scan2_kernel() {
    int acc = 0;
    for (int i = 0; i < SCAN_NBLK; i++) {
        g_bsum_ex[i] = acc;
        acc += g_bsum[i];
    }
}

__global__ void scan3_kernel() {
    int g = blockIdx.x * SCAN_CH + threadIdx.x;
    if (g < N_NODES) {
        int v = g_offs[g] + g_bsum_ex[blockIdx.x];
        g_offs[g] = v;
        g_wpos[g] = v;
    }
}

// ---------------- K4: exp, denom, CSR scatter ----------------
__global__ void edge_exp_kernel(const int* __restrict__ ei) {
    int e = blockIdx.x * blockDim.x + threadIdx.x;
    if (e >= N_EDGES) return;
    int d = ei[N_EDGES + e];
    float m  = finv(g_emax[d]);
    float ex = __expf(g_elog[e] - m);
    g_exv[e] = ex;
    atomicAdd(&g_denom[d], ex);
    int pos = atomicAdd(&g_wpos[d], 1);
    g_perm[pos] = e;
}

// ---------------- K5: per-node weighted aggregation (one warp per node) ----------------
__global__ void aggregate_kernel(const int* __restrict__ ei,
                                 const float* __restrict__ bias,
                                 float* __restrict__ out) {
    int node = blockIdx.x * 4 + (threadIdx.x >> 5);
    if (node >= N_NODES) return;
    int lane = threadIdx.x & 31;
    int beg = g_offs[node];
    int cnt = g_counts[node];

    float4 acc0 = make_float4(0.f, 0.f, 0.f, 0.f);
    float4 acc1 = make_float4(0.f, 0.f, 0.f, 0.f);

    for (int j = 0; j < cnt; j++) {
        int e = g_perm[beg + j];
        int s = ei[e];
        float w = g_exv[e];
        const float4* xl = reinterpret_cast<const float4*>(g_xl + (size_t)s * D_OUT);
        float4 a = xl[lane];
        float4 b = xl[lane + 32];
        acc0.x = fmaf(w, a.x, acc0.x); acc0.y = fmaf(w, a.y, acc0.y);
        acc0.z = fmaf(w, a.z, acc0.z); acc0.w = fmaf(w, a.w, acc0.w);
        acc1.x = fmaf(w, b.x, acc1.x); acc1.y = fmaf(w, b.y, acc1.y);
        acc1.z = fmaf(w, b.z, acc1.z); acc1.w = fmaf(w, b.w, acc1.w);
    }

    float rd = 1.f / (g_denom[node] + 1e-16f);
    const float4* bi = reinterpret_cast<const float4*>(bias);
    float4 b0 = bi[lane], b1 = bi[lane + 32];
    float4 o0 = make_float4(fmaf(acc0.x, rd, b0.x), fmaf(acc0.y, rd, b0.y),
                            fmaf(acc0.z, rd, b0.z), fmaf(acc0.w, rd, b0.w));
    float4 o1 = make_float4(fmaf(acc1.x, rd, b1.x), fmaf(acc1.y, rd, b1.y),
                            fmaf(acc1.z, rd, b1.z), fmaf(acc1.w, rd, b1.w));
    float4* op = reinterpret_cast<float4*>(out + (size_t)node * D_OUT);
    op[lane]      = o0;
    op[lane + 32] = o1;
}

// ---------------- launch ----------------
extern "C" void kernel_launch(void* const* d_in, const int* in_sizes, int n_in,
                              void* d_out, int out_size) {
    const float* x    = (const float*)d_in[0];
    const int*   ei   = (const int*)d_in[1];
    const float* W_l  = (const float*)d_in[2];
    const float* b_l  = (const float*)d_in[3];
    const float* W_r  = (const float*)d_in[4];
    const float* b_r  = (const float*)d_in[5];
    const float* att  = (const float*)d_in[6];
    const float* bias = (const float*)d_in[7];
    float* out = (float*)d_out;

    init_kernel<<<(N_NODES + 255) / 256, 256>>>();

    dim3 ggrid(2 * D_OUT / GBN, (N_NODES + GBM - 1) / GBM);   // (4, 782)
    gemm_tf32_kernel<<<ggrid, 256>>>(x, W_l, b_l, W_r, b_r);

    edge_logits_kernel<<<(N_EDGES + 7) / 8, 256>>>(ei, att);

    scan1_kernel<<<SCAN_NBLK, SCAN_CH>>>();
    scan2_kernel<<<1, 1>>>();
    scan3_kernel<<<SCAN_NBLK, SCAN_CH>>>();

    edge_exp_kernel<<<(N_EDGES + 255) / 256, 256>>>(ei);

    aggregate_kernel<<<(N_NODES + 3) / 4, 128>>>(ei, bias, out);
}

// round 3
// speedup vs baseline: 2.2469x; 1.0578x over previous
#include <cuda_runtime.h>

#define N_NODES 100000
#define N_EDGES 1600000
#define D_IN    480
#define D_OUT   256
#define NEG_SLOPE 0.2f

// ---------------- scratch (device globals: alloc-free) ----------------
__device__ float    g_xl[(size_t)N_NODES * D_OUT];
__device__ float    g_xr[(size_t)N_NODES * D_OUT];
__device__ float    g_elog[N_EDGES];
__device__ unsigned g_emax[N_NODES];
__device__ float    g_denom[N_NODES];
__device__ int      g_counts[N_NODES];
__device__ int      g_offs[N_NODES];
__device__ int      g_wpos[N_NODES];
__device__ int2     g_sw[N_EDGES];        // packed (src, exp) in CSR order
__device__ int      g_bsum[128];
__device__ int      g_bsum_ex[128];

__device__ __forceinline__ unsigned ford(float f) {
    unsigned u = __float_as_uint(f);
    return (u & 0x80000000u) ? ~u : (u | 0x80000000u);
}
__device__ __forceinline__ float finv(unsigned u) {
    return (u & 0x80000000u) ? __uint_as_float(u & 0x7fffffffu)
                             : __uint_as_float(~u);
}
__device__ __forceinline__ float tf32r(float x) {
    unsigned r;
    asm("cvt.rna.tf32.f32 %0, %1;" : "=r"(r) : "f"(x));
    return __uint_as_float(r);
}

// ---------------- K0: init ----------------
__global__ void init_kernel() {
    int i = blockIdx.x * blockDim.x + threadIdx.x;
    if (i < N_NODES) {
        g_emax[i]   = 0u;
        g_denom[i]  = 0.f;
        g_counts[i] = 0;
    }
}

// ---------------- K1: pipelined dual GEMM via tf32 mma.sync ----------------
// Combined column space [0,512): [0,256)->W_l->g_xl ; [256,512)->W_r->g_xr
// Block 128x128, BK=16, 2-stage smem pipeline. 8 warps, each 32(m) x 64(n).
#define GBM 128
#define GBN 128
#define GBK 16
#define PADA 20     // bank = (20m + k) % 32 distinct over 8 m-rows
#define PADB 136    // bank = (8k + n) % 32 distinct over 4k x 8n
#define NIT (D_IN / GBK)   // 30

__global__ __launch_bounds__(256, 2)
void gemm_tf32_kernel(const float* __restrict__ X,
                      const float* __restrict__ W_l, const float* __restrict__ b_l,
                      const float* __restrict__ W_r, const float* __restrict__ b_r) {
    __shared__ float As[2][GBM * PADA];
    __shared__ float Bs[2][GBK * PADB];

    int tx   = threadIdx.x;
    int lane = tx & 31;
    int wid  = tx >> 5;
    int warp_m = wid & 3;
    int warp_n = wid >> 2;

    int row0 = blockIdx.y * GBM;
    int col0 = blockIdx.x * GBN;

    const float* W; const float* bv; float* Y;
    int wc = col0;
    if (col0 < D_OUT) { W = W_l; bv = b_l; Y = g_xl; }
    else              { W = W_r; bv = b_r; Y = g_xr; wc = col0 - D_OUT; }

    // loader indices: A tile 128x16 = 512 float4 (2/thread); B tile 16x128 = 512 float4
    int am  = (tx >> 2);          // base row for i=0 (rows 0..63), i=1 adds 64
    int akq = (tx & 3);           // k-quad
    int bk  = (tx >> 5);          // base k for i=0 (0..7), i=1 adds 8
    int bnq = (tx & 31);          // n-quad

    float4 ra[2], rb[2];

    auto loadG = [&](int it) {
#pragma unroll
        for (int i = 0; i < 2; i++) {
            int m  = am + i * 64;
            int gr = row0 + m;
            float4 v = make_float4(0.f, 0.f, 0.f, 0.f);
            if (gr < N_NODES)
                v = *reinterpret_cast<const float4*>(X + (size_t)gr * D_IN + it * GBK + akq * 4);
            ra[i] = v;
        }
#pragma unroll
        for (int i = 0; i < 2; i++) {
            int k = bk + i * 8;
            rb[i] = *reinterpret_cast<const float4*>(W + (size_t)(it * GBK + k) * D_OUT + wc + bnq * 4);
        }
    };
    auto storeS = [&](int buf) {
#pragma unroll
        for (int i = 0; i < 2; i++) {
            int m = am + i * 64;
            float4 v = ra[i];
            v.x = tf32r(v.x); v.y = tf32r(v.y); v.z = tf32r(v.z); v.w = tf32r(v.w);
            *reinterpret_cast<float4*>(&As[buf][m * PADA + akq * 4]) = v;
        }
#pragma unroll
        for (int i = 0; i < 2; i++) {
            int k = bk + i * 8;
            float4 v = rb[i];
            v.x = tf32r(v.x); v.y = tf32r(v.y); v.z = tf32r(v.z); v.w = tf32r(v.w);
            *reinterpret_cast<float4*>(&Bs[buf][k * PADB + bnq * 4]) = v;
        }
    };

    float acc[2][8][4];
#pragma unroll
    for (int mt = 0; mt < 2; mt++)
#pragma unroll
        for (int nt = 0; nt < 8; nt++)
#pragma unroll
            for (int i = 0; i < 4; i++) acc[mt][nt][i] = 0.f;

    loadG(0);
    storeS(0);
    __syncthreads();

    for (int it = 0; it < NIT; it++) {
        int cur = it & 1;
        if (it + 1 < NIT) loadG(it + 1);

#pragma unroll
        for (int ks = 0; ks < 2; ks++) {
            int kk = ks * 8 + (lane & 3);
            unsigned a[2][4];
#pragma unroll
            for (int mt = 0; mt < 2; mt++) {
                int r = warp_m * 32 + mt * 16 + (lane >> 2);
                a[mt][0] = __float_as_uint(As[cur][r * PADA + kk]);
                a[mt][1] = __float_as_uint(As[cur][(r + 8) * PADA + kk]);
                a[mt][2] = __float_as_uint(As[cur][r * PADA + kk + 4]);
                a[mt][3] = __float_as_uint(As[cur][(r + 8) * PADA + kk + 4]);
            }
#pragma unroll
            for (int nt = 0; nt < 8; nt++) {
                int n = warp_n * 64 + nt * 8 + (lane >> 2);
                unsigned b0 = __float_as_uint(Bs[cur][kk * PADB + n]);
                unsigned b1 = __float_as_uint(Bs[cur][(kk + 4) * PADB + n]);
#pragma unroll
                for (int mt = 0; mt < 2; mt++) {
                    asm volatile(
                        "mma.sync.aligned.m16n8k8.row.col.f32.tf32.tf32.f32 "
                        "{%0,%1,%2,%3}, {%4,%5,%6,%7}, {%8,%9}, {%0,%1,%2,%3};"
                        : "+f"(acc[mt][nt][0]), "+f"(acc[mt][nt][1]),
                          "+f"(acc[mt][nt][2]), "+f"(acc[mt][nt][3])
                        : "r"(a[mt][0]), "r"(a[mt][1]), "r"(a[mt][2]), "r"(a[mt][3]),
                          "r"(b0), "r"(b1));
                }
            }
        }

        if (it + 1 < NIT) storeS((it + 1) & 1);
        __syncthreads();
    }

#pragma unroll
    for (int mt = 0; mt < 2; mt++) {
        int r = row0 + warp_m * 32 + mt * 16 + (lane >> 2);
#pragma unroll
        for (int nt = 0; nt < 8; nt++) {
            int c = wc + warp_n * 64 + nt * 8 + (lane & 3) * 2;
            if (r < N_NODES) {
                float2 v;
                v.x = acc[mt][nt][0] + bv[c];
                v.y = acc[mt][nt][1] + bv[c + 1];
                *reinterpret_cast<float2*>(Y + (size_t)r * D_OUT + c) = v;
            }
            if (r + 8 < N_NODES) {
                float2 v;
                v.x = acc[mt][nt][2] + bv[c];
                v.y = acc[mt][nt][3] + bv[c + 1];
                *reinterpret_cast<float2*>(Y + (size_t)(r + 8) * D_OUT + c) = v;
            }
        }
    }
}

// ---------------- K2: edge logits + segment max + degree histogram ----------------
__global__ void edge_logits_kernel(const int* __restrict__ ei,
                                   const float* __restrict__ att) {
    int e = blockIdx.x * 8 + (threadIdx.x >> 5);
    if (e >= N_EDGES) return;
    int lane = threadIdx.x & 31;
    int s = __ldg(&ei[e]);
    int d = __ldg(&ei[N_EDGES + e]);

    const float4* xl = reinterpret_cast<const float4*>(g_xl + (size_t)s * D_OUT);
    const float4* xr = reinterpret_cast<const float4*>(g_xr + (size_t)d * D_OUT);
    const float4* at = reinterpret_cast<const float4*>(att);

    float sum = 0.f;
#pragma unroll
    for (int i = 0; i < 2; i++) {
        int idx = lane + 32 * i;
        float4 a = xl[idx];
        float4 b = xr[idx];
        float4 c = at[idx];
        float h;
        h = a.x + b.x; h = h > 0.f ? h : NEG_SLOPE * h; sum = fmaf(c.x, h, sum);
        h = a.y + b.y; h = h > 0.f ? h : NEG_SLOPE * h; sum = fmaf(c.y, h, sum);
        h = a.z + b.z; h = h > 0.f ? h : NEG_SLOPE * h; sum = fmaf(c.z, h, sum);
        h = a.w + b.w; h = h > 0.f ? h : NEG_SLOPE * h; sum = fmaf(c.w, h, sum);
    }
#pragma unroll
    for (int o = 16; o > 0; o >>= 1) sum += __shfl_xor_sync(0xffffffffu, sum, o);

    if (lane == 0) {
        __stcs(&g_elog[e], sum);             // single-use: stream past L2
        atomicMax(&g_emax[d], ford(sum));
        atomicAdd(&g_counts[d], 1);
    }
}

// ---------------- K3: exclusive scan of counts -> offsets ----------------
#define SCAN_CH 1024
#define SCAN_NBLK ((N_NODES + SCAN_CH - 1) / SCAN_CH)   // 98

__global__ void scan1_kernel() {
    __shared__ int sh[SCAN_CH];
    int t = threadIdx.x;
    int g = blockIdx.x * SCAN_CH + t;
    int v = (g < N_NODES) ? g_counts[g] : 0;
    sh[t] = v;
    __syncthreads();
    for (int o = 1; o < SCAN_CH; o <<= 1) {
        int x = (t >= o) ? sh[t - o] : 0;
        __syncthreads();
        sh[t] += x;
        __syncthreads();
    }
    if (g < N_NODES) g_offs[g] = sh[t] - v;
    if (t == SCAN_CH - 1) g_bsum[blockIdx.x] = sh[t];
}

__global__ void scan2_kernel() {
    int acc = 0;
    for (int i = 0; i < SCAN_NBLK; i++) {
        g_bsum_ex[i] = acc;
        acc += g_bsum[i];
    }
}

__global__ void scan3_kernel() {
    int g = blockIdx.x * SCAN_CH + threadIdx.x;
    if (g < N_NODES) {
        int v = g_offs[g] + g_bsum_ex[blockIdx.x];
        g_offs[g] = v;
        g_wpos[g] = v;
    }
}

// ---------------- K4: exp, denom, packed CSR scatter ----------------
__global__ void edge_exp_kernel(const int* __restrict__ ei) {
    int e = blockIdx.x * blockDim.x + threadIdx.x;
    if (e >= N_EDGES) return;
    int s = __ldg(&ei[e]);
    int d = __ldg(&ei[N_EDGES + e]);
    float m  = finv(g_emax[d]);
    float ex = __expf(__ldcs(&g_elog[e]) - m);
    atomicAdd(&g_denom[d], ex);
    int pos = atomicAdd(&g_wpos[d], 1);
    g_sw[pos] = make_int2(s, __float_as_int(ex));
}

// ---------------- K5: per-node weighted aggregation (one warp per node) ----------------
__global__ void aggregate_kernel(const float* __restrict__ bias,
                                 float* __restrict__ out) {
    int node = blockIdx.x * 4 + (threadIdx.x >> 5);
    if (node >= N_NODES) return;
    int lane = threadIdx.x & 31;
    int beg = g_offs[node];
    int cnt = g_counts[node];

    float4 acc0 = make_float4(0.f, 0.f, 0.f, 0.f);
    float4 acc1 = make_float4(0.f, 0.f, 0.f, 0.f);

    int j = 0;
    for (; j + 2 <= cnt; j += 2) {
        int2 p0 = g_sw[beg + j];
        int2 p1 = g_sw[beg + j + 1];
        float w0 = __int_as_float(p0.y);
        float w1 = __int_as_float(p1.y);
        const float4* x0 = reinterpret_cast<const float4*>(g_xl + (size_t)p0.x * D_OUT);
        const float4* x1 = reinterpret_cast<const float4*>(g_xl + (size_t)p1.x * D_OUT);
        float4 a0 = x0[lane], b0 = x0[lane + 32];
        float4 a1 = x1[lane], b1 = x1[lane + 32];
        acc0.x = fmaf(w0, a0.x, acc0.x); acc0.y = fmaf(w0, a0.y, acc0.y);
        acc0.z = fmaf(w0, a0.z, acc0.z); acc0.w = fmaf(w0, a0.w, acc0.w);
        acc1.x = fmaf(w0, b0.x, acc1.x); acc1.y = fmaf(w0, b0.y, acc1.y);
        acc1.z = fmaf(w0, b0.z, acc1.z); acc1.w = fmaf(w0, b0.w, acc1.w);
        acc0.x = fmaf(w1, a1.x, acc0.x); acc0.y = fmaf(w1, a1.y, acc0.y);
        acc0.z = fmaf(w1, a1.z, acc0.z); acc0.w = fmaf(w1, a1.w, acc0.w);
        acc1.x = fmaf(w1, b1.x, acc1.x); acc1.y = fmaf(w1, b1.y, acc1.y);
        acc1.z = fmaf(w1, b1.z, acc1.z); acc1.w = fmaf(w1, b1.w, acc1.w);
    }
    if (j < cnt) {
        int2 p0 = g_sw[beg + j];
        float w0 = __int_as_float(p0.y);
        const float4* x0 = reinterpret_cast<const float4*>(g_xl + (size_t)p0.x * D_OUT);
        float4 a0 = x0[lane], b0 = x0[lane + 32];
        acc0.x = fmaf(w0, a0.x, acc0.x); acc0.y = fmaf(w0, a0.y, acc0.y);
        acc0.z = fmaf(w0, a0.z, acc0.z); acc0.w = fmaf(w0, a0.w, acc0.w);
        acc1.x = fmaf(w0, b0.x, acc1.x); acc1.y = fmaf(w0, b0.y, acc1.y);
        acc1.z = fmaf(w0, b0.z, acc1.z); acc1.w = fmaf(w0, b0.w, acc1.w);
    }

    float rd = 1.f / (g_denom[node] + 1e-16f);
    const float4* bi = reinterpret_cast<const float4*>(bias);
    float4 b0 = bi[lane], b1 = bi[lane + 32];
    float4 o0 = make_float4(fmaf(acc0.x, rd, b0.x), fmaf(acc0.y, rd, b0.y),
                            fmaf(acc0.z, rd, b0.z), fmaf(acc0.w, rd, b0.w));
    float4 o1 = make_float4(fmaf(acc1.x, rd, b1.x), fmaf(acc1.y, rd, b1.y),
                            fmaf(acc1.z, rd, b1.z), fmaf(acc1.w, rd, b1.w));
    float4* op = reinterpret_cast<float4*>(out + (size_t)node * D_OUT);
    op[lane]      = o0;
    op[lane + 32] = o1;
}

// ---------------- launch ----------------
extern "C" void kernel_launch(void* const* d_in, const int* in_sizes, int n_in,
                              void* d_out, int out_size) {
    const float* x    = (const float*)d_in[0];
    const int*   ei   = (const int*)d_in[1];
    const float* W_l  = (const float*)d_in[2];
    const float* b_l  = (const float*)d_in[3];
    const float* W_r  = (const float*)d_in[4];
    const float* b_r  = (const float*)d_in[5];
    const float* att  = (const float*)d_in[6];
    const float* bias = (const float*)d_in[7];
    float* out = (float*)d_out;

    init_kernel<<<(N_NODES + 255) / 256, 256>>>();

    dim3 ggrid(2 * D_OUT / GBN, (N_NODES + GBM - 1) / GBM);   // (4, 782)
    gemm_tf32_kernel<<<ggrid, 256>>>(x, W_l, b_l, W_r, b_r);

    edge_logits_kernel<<<(N_EDGES + 7) / 8, 256>>>(ei, att);

    scan1_kernel<<<SCAN_NBLK, SCAN_CH>>>();
    scan2_kernel<<<1, 1>>>();
    scan3_kernel<<<SCAN_NBLK, SCAN_CH>>>();

    edge_exp_kernel<<<(N_EDGES + 255) / 256, 256>>>(ei);

    aggregate_kernel<<<(N_NODES + 3) / 4, 128>>>(bias, out);
}

// round 4
// speedup vs baseline: 3.1067x; 1.3827x over previous
#include <cuda_runtime.h>

#define N_NODES 100000
#define N_EDGES 1600000
#define D_IN    480
#define D_OUT   256
#define NEG_SLOPE 0.2f

// ---------------- scratch ----------------
__device__ float g_xl[(size_t)N_NODES * D_OUT];
__device__ float g_xr[(size_t)N_NODES * D_OUT];
__device__ int   g_counts[N_NODES];
__device__ int   g_offs[N_NODES];
__device__ int   g_wpos[N_NODES];
__device__ int   g_csrc[N_EDGES];      // src ids grouped by dst
__device__ int   g_bsum[128];
__device__ int   g_bsum_ex[128];

__device__ __forceinline__ float tf32r(float x) {
    unsigned r;
    asm("cvt.rna.tf32.f32 %0, %1;" : "=r"(r) : "f"(x));
    return __uint_as_float(r);
}

// ---------------- K0: init ----------------
__global__ void init_kernel() {
    int i = blockIdx.x * blockDim.x + threadIdx.x;
    if (i < N_NODES) g_counts[i] = 0;
}

// ---------------- K2: dst histogram ----------------
__global__ void hist_kernel(const int* __restrict__ ei) {
    int e = blockIdx.x * blockDim.x + threadIdx.x;
    if (e < N_EDGES) atomicAdd(&g_counts[ei[N_EDGES + e]], 1);
}

// ---------------- K1: pipelined dual GEMM via tf32 mma.sync ----------------
#define GBM 128
#define GBN 128
#define GBK 16
#define PADA 20
#define PADB 136
#define NIT (D_IN / GBK)   // 30

__global__ __launch_bounds__(256, 2)
void gemm_tf32_kernel(const float* __restrict__ X,
                      const float* __restrict__ W_l, const float* __restrict__ b_l,
                      const float* __restrict__ W_r, const float* __restrict__ b_r) {
    __shared__ float As[2][GBM * PADA];
    __shared__ float Bs[2][GBK * PADB];

    int tx   = threadIdx.x;
    int lane = tx & 31;
    int wid  = tx >> 5;
    int warp_m = wid & 3;
    int warp_n = wid >> 2;

    int row0 = blockIdx.y * GBM;
    int col0 = blockIdx.x * GBN;

    const float* W; const float* bv; float* Y;
    int wc = col0;
    if (col0 < D_OUT) { W = W_l; bv = b_l; Y = g_xl; }
    else              { W = W_r; bv = b_r; Y = g_xr; wc = col0 - D_OUT; }

    int am  = (tx >> 2);
    int akq = (tx & 3);
    int bk  = (tx >> 5);
    int bnq = (tx & 31);

    float4 ra[2], rb[2];

    auto loadG = [&](int it) {
#pragma unroll
        for (int i = 0; i < 2; i++) {
            int m  = am + i * 64;
            int gr = row0 + m;
            float4 v = make_float4(0.f, 0.f, 0.f, 0.f);
            if (gr < N_NODES)
                v = *reinterpret_cast<const float4*>(X + (size_t)gr * D_IN + it * GBK + akq * 4);
            ra[i] = v;
        }
#pragma unroll
        for (int i = 0; i < 2; i++) {
            int k = bk + i * 8;
            rb[i] = *reinterpret_cast<const float4*>(W + (size_t)(it * GBK + k) * D_OUT + wc + bnq * 4);
        }
    };
    auto storeS = [&](int buf) {
#pragma unroll
        for (int i = 0; i < 2; i++) {
            int m = am + i * 64;
            float4 v = ra[i];
            v.x = tf32r(v.x); v.y = tf32r(v.y); v.z = tf32r(v.z); v.w = tf32r(v.w);
            *reinterpret_cast<float4*>(&As[buf][m * PADA + akq * 4]) = v;
        }
#pragma unroll
        for (int i = 0; i < 2; i++) {
            int k = bk + i * 8;
            float4 v = rb[i];
            v.x = tf32r(v.x); v.y = tf32r(v.y); v.z = tf32r(v.z); v.w = tf32r(v.w);
            *reinterpret_cast<float4*>(&Bs[buf][k * PADB + bnq * 4]) = v;
        }
    };

    float acc[2][8][4];
#pragma unroll
    for (int mt = 0; mt < 2; mt++)
#pragma unroll
        for (int nt = 0; nt < 8; nt++)
#pragma unroll
            for (int i = 0; i < 4; i++) acc[mt][nt][i] = 0.f;

    loadG(0);
    storeS(0);
    __syncthreads();

    for (int it = 0; it < NIT; it++) {
        int cur = it & 1;
        if (it + 1 < NIT) loadG(it + 1);

#pragma unroll
        for (int ks = 0; ks < 2; ks++) {
            int kk = ks * 8 + (lane & 3);
            unsigned a[2][4];
#pragma unroll
            for (int mt = 0; mt < 2; mt++) {
                int r = warp_m * 32 + mt * 16 + (lane >> 2);
                a[mt][0] = __float_as_uint(As[cur][r * PADA + kk]);
                a[mt][1] = __float_as_uint(As[cur][(r + 8) * PADA + kk]);
                a[mt][2] = __float_as_uint(As[cur][r * PADA + kk + 4]);
                a[mt][3] = __float_as_uint(As[cur][(r + 8) * PADA + kk + 4]);
            }
#pragma unroll
            for (int nt = 0; nt < 8; nt++) {
                int n = warp_n * 64 + nt * 8 + (lane >> 2);
                unsigned b0 = __float_as_uint(Bs[cur][kk * PADB + n]);
                unsigned b1 = __float_as_uint(Bs[cur][(kk + 4) * PADB + n]);
#pragma unroll
                for (int mt = 0; mt < 2; mt++) {
                    asm volatile(
                        "mma.sync.aligned.m16n8k8.row.col.f32.tf32.tf32.f32 "
                        "{%0,%1,%2,%3}, {%4,%5,%6,%7}, {%8,%9}, {%0,%1,%2,%3};"
                        : "+f"(acc[mt][nt][0]), "+f"(acc[mt][nt][1]),
                          "+f"(acc[mt][nt][2]), "+f"(acc[mt][nt][3])
                        : "r"(a[mt][0]), "r"(a[mt][1]), "r"(a[mt][2]), "r"(a[mt][3]),
                          "r"(b0), "r"(b1));
                }
            }
        }

        if (it + 1 < NIT) storeS((it + 1) & 1);
        __syncthreads();
    }

#pragma unroll
    for (int mt = 0; mt < 2; mt++) {
        int r = row0 + warp_m * 32 + mt * 16 + (lane >> 2);
#pragma unroll
        for (int nt = 0; nt < 8; nt++) {
            int c = wc + warp_n * 64 + nt * 8 + (lane & 3) * 2;
            if (r < N_NODES) {
                float2 v;
                v.x = acc[mt][nt][0] + bv[c];
                v.y = acc[mt][nt][1] + bv[c + 1];
                *reinterpret_cast<float2*>(Y + (size_t)r * D_OUT + c) = v;
            }
            if (r + 8 < N_NODES) {
                float2 v;
                v.x = acc[mt][nt][2] + bv[c];
                v.y = acc[mt][nt][3] + bv[c + 1];
                *reinterpret_cast<float2*>(Y + (size_t)(r + 8) * D_OUT + c) = v;
            }
        }
    }
}

// ---------------- K3: exclusive scan ----------------
#define SCAN_CH 1024
#define SCAN_NBLK ((N_NODES + SCAN_CH - 1) / SCAN_CH)

__global__ void scan1_kernel() {
    __shared__ int sh[SCAN_CH];
    int t = threadIdx.x;
    int g = blockIdx.x * SCAN_CH + t;
    int v = (g < N_NODES) ? g_counts[g] : 0;
    sh[t] = v;
    __syncthreads();
    for (int o = 1; o < SCAN_CH; o <<= 1) {
        int x = (t >= o) ? sh[t - o] : 0;
        __syncthreads();
        sh[t] += x;
        __syncthreads();
    }
    if (g < N_NODES) g_offs[g] = sh[t] - v;
    if (t == SCAN_CH - 1) g_bsum[blockIdx.x] = sh[t];
}

__global__ void scan2_kernel() {
    int acc = 0;
    for (int i = 0; i < SCAN_NBLK; i++) {
        g_bsum_ex[i] = acc;
        acc += g_bsum[i];
    }
}

__global__ void scan3_kernel() {
    int g = blockIdx.x * SCAN_CH + threadIdx.x;
    if (g < N_NODES) {
        int v = g_offs[g] + g_bsum_ex[blockIdx.x];
        g_offs[g] = v;
        g_wpos[g] = v;
    }
}

// ---------------- K4: CSR scatter of src ids ----------------
__global__ void scatter_kernel(const int* __restrict__ ei) {
    int e = blockIdx.x * blockDim.x + threadIdx.x;
    if (e >= N_EDGES) return;
    int s = __ldg(&ei[e]);
    int d = __ldg(&ei[N_EDGES + e]);
    int pos = atomicAdd(&g_wpos[d], 1);
    g_csrc[pos] = s;
}

// ---------------- K5: fused logits+softmax+aggregate (one warp per node) ----------------
__global__ __launch_bounds__(256)
void fused_node_kernel(const float* __restrict__ att,
                       const float* __restrict__ bias,
                       float* __restrict__ out) {
    int node = blockIdx.x * 8 + (threadIdx.x >> 5);
    if (node >= N_NODES) return;
    int lane = threadIdx.x & 31;
    int beg = g_offs[node];
    int cnt = g_counts[node];

    // registers: xr row, att (8 floats each as 2 float4)
    const float4* xrp = reinterpret_cast<const float4*>(g_xr + (size_t)node * D_OUT);
    const float4* atp = reinterpret_cast<const float4*>(att);
    float4 xr0 = xrp[lane], xr1 = xrp[lane + 32];
    float4 at0 = atp[lane], at1 = atp[lane + 32];

    float4 acc0 = make_float4(0.f, 0.f, 0.f, 0.f);
    float4 acc1 = make_float4(0.f, 0.f, 0.f, 0.f);
    float denom = 0.f;

    // batched src load: one coalesced read per 32 edges, broadcast by shfl
    int s_reg = (lane < cnt) ? g_csrc[beg + lane] : 0;
    int batch = 0;   // index of batch currently in s_reg

    int j = 0;
    for (; j + 2 <= cnt; j += 2) {
        if ((j >> 5) != batch) {
            batch = j >> 5;
            int idx = beg + batch * 32 + lane;
            s_reg = (batch * 32 + lane < cnt) ? g_csrc[idx] : 0;
        }
        int s0 = __shfl_sync(0xffffffffu, s_reg, j & 31);
        int s1;
        if (((j + 1) >> 5) != batch) {   // second edge falls in next batch
            batch = (j + 1) >> 5;
            int idx = beg + batch * 32 + lane;
            s_reg = (batch * 32 + lane < cnt) ? g_csrc[idx] : 0;
            s1 = __shfl_sync(0xffffffffu, s_reg, (j + 1) & 31);
        } else {
            s1 = __shfl_sync(0xffffffffu, s_reg, (j + 1) & 31);
        }

        const float4* xp0 = reinterpret_cast<const float4*>(g_xl + (size_t)s0 * D_OUT);
        const float4* xp1 = reinterpret_cast<const float4*>(g_xl + (size_t)s1 * D_OUT);
        float4 a0 = xp0[lane], b0 = xp0[lane + 32];
        float4 a1 = xp1[lane], b1 = xp1[lane + 32];

        float p0 = 0.f, p1 = 0.f, h;
        h = a0.x + xr0.x; h = h > 0.f ? h : NEG_SLOPE * h; p0 = fmaf(at0.x, h, p0);
        h = a0.y + xr0.y; h = h > 0.f ? h : NEG_SLOPE * h; p0 = fmaf(at0.y, h, p0);
        h = a0.z + xr0.z; h = h > 0.f ? h : NEG_SLOPE * h; p0 = fmaf(at0.z, h, p0);
        h = a0.w + xr0.w; h = h > 0.f ? h : NEG_SLOPE * h; p0 = fmaf(at0.w, h, p0);
        h = b0.x + xr1.x; h = h > 0.f ? h : NEG_SLOPE * h; p0 = fmaf(at1.x, h, p0);
        h = b0.y + xr1.y; h = h > 0.f ? h : NEG_SLOPE * h; p0 = fmaf(at1.y, h, p0);
        h = b0.z + xr1.z; h = h > 0.f ? h : NEG_SLOPE * h; p0 = fmaf(at1.z, h, p0);
        h = b0.w + xr1.w; h = h > 0.f ? h : NEG_SLOPE * h; p0 = fmaf(at1.w, h, p0);
        h = a1.x + xr0.x; h = h > 0.f ? h : NEG_SLOPE * h; p1 = fmaf(at0.x, h, p1);
        h = a1.y + xr0.y; h = h > 0.f ? h : NEG_SLOPE * h; p1 = fmaf(at0.y, h, p1);
        h = a1.z + xr0.z; h = h > 0.f ? h : NEG_SLOPE * h; p1 = fmaf(at0.z, h, p1);
        h = a1.w + xr0.w; h = h > 0.f ? h : NEG_SLOPE * h; p1 = fmaf(at0.w, h, p1);
        h = b1.x + xr1.x; h = h > 0.f ? h : NEG_SLOPE * h; p1 = fmaf(at1.x, h, p1);
        h = b1.y + xr1.y; h = h > 0.f ? h : NEG_SLOPE * h; p1 = fmaf(at1.y, h, p1);
        h = b1.z + xr1.z; h = h > 0.f ? h : NEG_SLOPE * h; p1 = fmaf(at1.z, h, p1);
        h = b1.w + xr1.w; h = h > 0.f ? h : NEG_SLOPE * h; p1 = fmaf(at1.w, h, p1);

#pragma unroll
        for (int o = 16; o > 0; o >>= 1) {
            p0 += __shfl_xor_sync(0xffffffffu, p0, o);
            p1 += __shfl_xor_sync(0xffffffffu, p1, o);
        }
        float w0 = __expf(p0);
        float w1 = __expf(p1);
        denom += w0 + w1;
        acc0.x = fmaf(w0, a0.x, acc0.x); acc0.y = fmaf(w0, a0.y, acc0.y);
        acc0.z = fmaf(w0, a0.z, acc0.z); acc0.w = fmaf(w0, a0.w, acc0.w);
        acc1.x = fmaf(w0, b0.x, acc1.x); acc1.y = fmaf(w0, b0.y, acc1.y);
        acc1.z = fmaf(w0, b0.z, acc1.z); acc1.w = fmaf(w0, b0.w, acc1.w);
        acc0.x = fmaf(w1, a1.x, acc0.x); acc0.y = fmaf(w1, a1.y, acc0.y);
        acc0.z = fmaf(w1, a1.z, acc0.z); acc0.w = fmaf(w1, a1.w, acc0.w);
        acc1.x = fmaf(w1, b1.x, acc1.x); acc1.y = fmaf(w1, b1.y, acc1.y);
        acc1.z = fmaf(w1, b1.z, acc1.z); acc1.w = fmaf(w1, b1.w, acc1.w);
    }
    if (j < cnt) {
        if ((j >> 5) != batch) {
            batch = j >> 5;
            int idx = beg + batch * 32 + lane;
            s_reg = (batch * 32 + lane < cnt) ? g_csrc[idx] : 0;
        }
        int s0 = __shfl_sync(0xffffffffu, s_reg, j & 31);
        const float4* xp0 = reinterpret_cast<const float4*>(g_xl + (size_t)s0 * D_OUT);
        float4 a0 = xp0[lane], b0 = xp0[lane + 32];
        float p0 = 0.f, h;
        h = a0.x + xr0.x; h = h > 0.f ? h : NEG_SLOPE * h; p0 = fmaf(at0.x, h, p0);
        h = a0.y + xr0.y; h = h > 0.f ? h : NEG_SLOPE * h; p0 = fmaf(at0.y, h, p0);
        h = a0.z + xr0.z; h = h > 0.f ? h : NEG_SLOPE * h; p0 = fmaf(at0.z, h, p0);
        h = a0.w + xr0.w; h = h > 0.f ? h : NEG_SLOPE * h; p0 = fmaf(at0.w, h, p0);
        h = b0.x + xr1.x; h = h > 0.f ? h : NEG_SLOPE * h; p0 = fmaf(at1.x, h, p0);
        h = b0.y + xr1.y; h = h > 0.f ? h : NEG_SLOPE * h; p0 = fmaf(at1.y, h, p0);
        h = b0.z + xr1.z; h = h > 0.f ? h : NEG_SLOPE * h; p0 = fmaf(at1.z, h, p0);
        h = b0.w + xr1.w; h = h > 0.f ? h : NEG_SLOPE * h; p0 = fmaf(at1.w, h, p0);
#pragma unroll
        for (int o = 16; o > 0; o >>= 1) p0 += __shfl_xor_sync(0xffffffffu, p0, o);
        float w0 = __expf(p0);
        denom += w0;
        acc0.x = fmaf(w0, a0.x, acc0.x); acc0.y = fmaf(w0, a0.y, acc0.y);
        acc0.z = fmaf(w0, a0.z, acc0.z); acc0.w = fmaf(w0, a0.w, acc0.w);
        acc1.x = fmaf(w0, b0.x, acc1.x); acc1.y = fmaf(w0, b0.y, acc1.y);
        acc1.z = fmaf(w0, b0.z, acc1.z); acc1.w = fmaf(w0, b0.w, acc1.w);
    }

    float rd = 1.f / (denom + 1e-16f);
    const float4* bi = reinterpret_cast<const float4*>(bias);
    float4 bb0 = bi[lane], bb1 = bi[lane + 32];
    float4 o0 = make_float4(fmaf(acc0.x, rd, bb0.x), fmaf(acc0.y, rd, bb0.y),
                            fmaf(acc0.z, rd, bb0.z), fmaf(acc0.w, rd, bb0.w));
    float4 o1 = make_float4(fmaf(acc1.x, rd, bb1.x), fmaf(acc1.y, rd, bb1.y),
                            fmaf(acc1.z, rd, bb1.z), fmaf(acc1.w, rd, bb1.w));
    float4* op = reinterpret_cast<float4*>(out + (size_t)node * D_OUT);
    op[lane]      = o0;
    op[lane + 32] = o1;
}

// ---------------- launch ----------------
extern "C" void kernel_launch(void* const* d_in, const int* in_sizes, int n_in,
                              void* d_out, int out_size) {
    const float* x    = (const float*)d_in[0];
    const int*   ei   = (const int*)d_in[1];
    const float* W_l  = (const float*)d_in[2];
    const float* b_l  = (const float*)d_in[3];
    const float* W_r  = (const float*)d_in[4];
    const float* b_r  = (const float*)d_in[5];
    const float* att  = (const float*)d_in[6];
    const float* bias = (const float*)d_in[7];
    float* out = (float*)d_out;

    init_kernel<<<(N_NODES + 255) / 256, 256>>>();
    hist_kernel<<<(N_EDGES + 255) / 256, 256>>>(ei);

    dim3 ggrid(2 * D_OUT / GBN, (N_NODES + GBM - 1) / GBM);
    gemm_tf32_kernel<<<ggrid, 256>>>(x, W_l, b_l, W_r, b_r);

    scan1_kernel<<<SCAN_NBLK, SCAN_CH>>>();
    scan2_kernel<<<1, 1>>>();
    scan3_kernel<<<SCAN_NBLK, SCAN_CH>>>();

    scatter_kernel<<<(N_EDGES + 255) / 256, 256>>>(ei);

    fused_node_kernel<<<(N_NODES + 7) / 8, 256>>>(att, bias, out);
}